// round 9
// baseline (speedup 1.0000x reference)
#include <cuda_runtime.h>
#include <cuda_bf16.h>
#include <math.h>

// NTXent loss, t = 0.5.
// loss = mean_i [ log( sum_{j != i} exp(dot(hn_i, hn_j)/t) ) - dot(h1n_i, h2n_i)/t ]
//
// K1: normalize h1/h2 rows -> bf16 H[16384,128], fp32 pos dots, zero rowsums
// K2: bf16 mma.sync GEMM (M=N=16384, K=128) fused with exp() and row-sum
// K3: final log + mean reduction
//
// Diagonal of exp(S/t) is exp(1/t) = e^2 analytically (normalized rows), so we
// include the (bf16-quantized) diagonal in the row sums and subtract e^2.

#define NROWS 16384
#define NPAIR 8192
#define D     128

// padded smem stride (bf16 units): 136 -> word stride 68 == 4 (mod 32) banks,
// makes all fragment LDS.32 patterns (4g + tg) conflict-free.
#define LDT 136
#define SMEM_BYTES (2 * 128 * LDT * sizeof(__nv_bfloat16))  // 69632

__device__ __align__(16) __nv_bfloat16 g_H[(size_t)NROWS * D];
__device__ float g_rowsum[NROWS];
__device__ float g_pos[NPAIR];

__device__ __forceinline__ float ex2f(float x) {
    float y;
    asm("ex2.approx.ftz.f32 %0, %1;" : "=f"(y) : "f"(x));
    return y;
}

__device__ __forceinline__ void mma16816(float c[4], const unsigned a[4], const unsigned b[2]) {
    asm volatile(
        "mma.sync.aligned.m16n8k16.row.col.f32.bf16.bf16.f32 "
        "{%0,%1,%2,%3}, {%4,%5,%6,%7}, {%8,%9}, {%0,%1,%2,%3};"
        : "+f"(c[0]), "+f"(c[1]), "+f"(c[2]), "+f"(c[3])
        : "r"(a[0]), "r"(a[1]), "r"(a[2]), "r"(a[3]), "r"(b[0]), "r"(b[1]));
}

// ---------------------------------------------------------------------------
// K1: one warp per pair i. Computes s11, s22, s12 in one pass, writes both
// normalized rows as bf16 into g_H, pos dot (fp32), zeroes g_rowsum.
// ---------------------------------------------------------------------------
__global__ void norm_kernel(const float* __restrict__ h1, const float* __restrict__ h2) {
    const int gwarp = (blockIdx.x * blockDim.x + threadIdx.x) >> 5;
    const int lane  = threadIdx.x & 31;
    if (gwarp >= NPAIR) return;

    const float4 a = reinterpret_cast<const float4*>(h1 + (size_t)gwarp * D)[lane];
    const float4 b = reinterpret_cast<const float4*>(h2 + (size_t)gwarp * D)[lane];

    float s11 = a.x * a.x + a.y * a.y + a.z * a.z + a.w * a.w;
    float s22 = b.x * b.x + b.y * b.y + b.z * b.z + b.w * b.w;
    float s12 = a.x * b.x + a.y * b.y + a.z * b.z + a.w * b.w;

    #pragma unroll
    for (int off = 16; off > 0; off >>= 1) {
        s11 += __shfl_xor_sync(0xffffffffu, s11, off);
        s22 += __shfl_xor_sync(0xffffffffu, s22, off);
        s12 += __shfl_xor_sync(0xffffffffu, s12, off);
    }

    const float i1 = rsqrtf(s11);
    const float i2 = rsqrtf(s22);

    __nv_bfloat162* r1 = reinterpret_cast<__nv_bfloat162*>(g_H + (size_t)gwarp * D);
    __nv_bfloat162* r2 = reinterpret_cast<__nv_bfloat162*>(g_H + (size_t)(gwarp + NPAIR) * D);
    r1[lane * 2 + 0] = __floats2bfloat162_rn(a.x * i1, a.y * i1);
    r1[lane * 2 + 1] = __floats2bfloat162_rn(a.z * i1, a.w * i1);
    r2[lane * 2 + 0] = __floats2bfloat162_rn(b.x * i2, b.y * i2);
    r2[lane * 2 + 1] = __floats2bfloat162_rn(b.z * i2, b.w * i2);

    if (lane == 0) {
        g_pos[gwarp] = s12 * i1 * i2;
        g_rowsum[gwarp] = 0.0f;
        g_rowsum[gwarp + NPAIR] = 0.0f;
    }
}

// ---------------------------------------------------------------------------
// K2: CTA computes 128x128 tile of S = H H^T, K=128 in one shot.
// 4 warps (2x2), 64x64 warp tile, m16n8k16 bf16 mma.
// Epilogue: exp(2*s) via ex2, per-row partial sums -> atomicAdd(g_rowsum).
// ---------------------------------------------------------------------------
__global__ void __launch_bounds__(128) gemm_kernel() {
    extern __shared__ __nv_bfloat16 smem[];
    __nv_bfloat16* sA = smem;               // 128 x LDT
    __nv_bfloat16* sB = smem + 128 * LDT;   // 128 x LDT

    const int tid = threadIdx.x;
    const int bi = blockIdx.y;  // row tile
    const int bj = blockIdx.x;  // col tile

    // load both 128x128 bf16 tiles (rows of H), coalesced 16B chunks
    #pragma unroll
    for (int i = tid; i < 128 * 16; i += 128) {
        const int r = i >> 4, c = i & 15;
        *reinterpret_cast<uint4*>(sA + r * LDT + c * 8) =
            *reinterpret_cast<const uint4*>(g_H + (size_t)(bi * 128 + r) * D + c * 8);
        *reinterpret_cast<uint4*>(sB + r * LDT + c * 8) =
            *reinterpret_cast<const uint4*>(g_H + (size_t)(bj * 128 + r) * D + c * 8);
    }
    __syncthreads();

    const int warp = tid >> 5;
    const int lane = tid & 31;
    const int wm = warp >> 1;       // 0..1
    const int wn = warp & 1;        // 0..1
    const int g  = lane >> 2;       // 0..7
    const int tg = lane & 3;        // 0..3

    float acc[4][8][4];
    #pragma unroll
    for (int f = 0; f < 4; ++f)
        #pragma unroll
        for (int j = 0; j < 8; ++j)
            #pragma unroll
            for (int q = 0; q < 4; ++q) acc[f][j][q] = 0.0f;

    const __nv_bfloat16* Ab = sA + (wm * 64) * LDT;
    const __nv_bfloat16* Bb = sB + (wn * 64) * LDT;

    #pragma unroll
    for (int k = 0; k < 8; ++k) {
        const int k0 = k * 16 + tg * 2;
        unsigned a[4][4], b[8][2];
        #pragma unroll
        for (int f = 0; f < 4; ++f) {
            const __nv_bfloat16* p = Ab + (f * 16 + g) * LDT + k0;
            a[f][0] = *reinterpret_cast<const unsigned*>(p);
            a[f][1] = *reinterpret_cast<const unsigned*>(p + 8 * LDT);
            a[f][2] = *reinterpret_cast<const unsigned*>(p + 8);
            a[f][3] = *reinterpret_cast<const unsigned*>(p + 8 * LDT + 8);
        }
        #pragma unroll
        for (int j = 0; j < 8; ++j) {
            const __nv_bfloat16* p = Bb + (j * 8 + g) * LDT + k0;
            b[j][0] = *reinterpret_cast<const unsigned*>(p);
            b[j][1] = *reinterpret_cast<const unsigned*>(p + 8);
        }
        #pragma unroll
        for (int f = 0; f < 4; ++f)
            #pragma unroll
            for (int j = 0; j < 8; ++j)
                mma16816(acc[f][j], a[f], b[j]);
    }

    // exp(s/t) = exp(2 s) = 2^(2 log2e * s)
    const float KK = 2.8853900817779268f;

    #pragma unroll
    for (int f = 0; f < 4; ++f) {
        float slo = 0.0f, shi = 0.0f;
        #pragma unroll
        for (int j = 0; j < 8; ++j) {
            slo += ex2f(acc[f][j][0] * KK) + ex2f(acc[f][j][1] * KK);
            shi += ex2f(acc[f][j][2] * KK) + ex2f(acc[f][j][3] * KK);
        }
        // reduce over the 4 lanes of each quad (columns)
        slo += __shfl_xor_sync(0xffffffffu, slo, 1);
        slo += __shfl_xor_sync(0xffffffffu, slo, 2);
        shi += __shfl_xor_sync(0xffffffffu, shi, 1);
        shi += __shfl_xor_sync(0xffffffffu, shi, 2);
        if (tg == 0) {
            const int row = bi * 128 + wm * 64 + f * 16 + g;
            atomicAdd(&g_rowsum[row], slo);
            atomicAdd(&g_rowsum[row + 8], shi);
        }
    }
}

// ---------------------------------------------------------------------------
// K3: loss = mean( log(rowsum_i - e^2) - 2 * pos[i mod NPAIR] )
// ---------------------------------------------------------------------------
__global__ void loss_kernel(float* __restrict__ out) {
    __shared__ float red[256];
    const float E2 = 7.389056098930650f;  // exp(1/t) = e^2
    float s = 0.0f;
    for (int i = threadIdx.x; i < NROWS; i += 256) {
        const float denom = g_rowsum[i] - E2;
        s += logf(denom) - 2.0f * g_pos[i & (NPAIR - 1)];
    }
    red[threadIdx.x] = s;
    __syncthreads();
    #pragma unroll
    for (int off = 128; off > 0; off >>= 1) {
        if (threadIdx.x < off) red[threadIdx.x] += red[threadIdx.x + off];
        __syncthreads();
    }
    if (threadIdx.x == 0) out[0] = red[0] * (1.0f / (float)NROWS);
}

extern "C" void kernel_launch(void* const* d_in, const int* in_sizes, int n_in,
                              void* d_out, int out_size) {
    const float* h1 = (const float*)d_in[0];
    const float* h2 = (const float*)d_in[1];

    cudaFuncSetAttribute(gemm_kernel, cudaFuncAttributeMaxDynamicSharedMemorySize,
                         (int)SMEM_BYTES);

    norm_kernel<<<NPAIR / 8, 256>>>(h1, h2);
    gemm_kernel<<<dim3(128, 128), 128, SMEM_BYTES>>>();
    loss_kernel<<<1, 256>>>((float*)d_out);
}

// round 10
// speedup vs baseline: 1.4391x; 1.4391x over previous
#include <cuda_runtime.h>
#include <cuda_bf16.h>
#include <math.h>

// NTXent loss, t = 0.5.
// loss = mean_i [ log( sum_{j != i} exp(dot(hn_i, hn_j)/t) ) - dot(h1n_i, h2n_i)/t ]
//
// K1: normalize h1/h2 rows -> bf16 H[16384,128], fp32 pos dots, zero rowsums
// K2: SYMMETRIC bf16 mma.sync GEMM: only upper-triangular 128x128 tiles
//     (8256 of 16384). Off-diagonal tiles contribute exp() values to BOTH
//     the row sums of the bi-block (row reduce) and of the bj-block
//     (column reduce, since S is symmetric). Diagonal tiles: rows only.
// K3: final log + mean reduction
//
// Diagonal of exp(S/t) is exp(1/t) = e^2 analytically (normalized rows), so we
// include the (bf16-quantized) diagonal in the row sums and subtract e^2.

#define NROWS 16384
#define NPAIR 8192
#define D     128

// padded smem stride (bf16 units): 136 -> word stride 68 == 4 (mod 32) banks,
// makes all fragment LDS.32 patterns (4g + tg) conflict-free.
#define LDT 136
#define SMEM_BYTES (2 * 128 * LDT * sizeof(__nv_bfloat16))  // 69632

#define NTILE     128                         // 16384 / 128
#define NTRI      (NTILE * (NTILE + 1) / 2)   // 8256 upper-tri tiles

__device__ __align__(16) __nv_bfloat16 g_H[(size_t)NROWS * D];
__device__ float g_rowsum[NROWS];
__device__ float g_pos[NPAIR];

__device__ __forceinline__ float ex2f(float x) {
    float y;
    asm("ex2.approx.ftz.f32 %0, %1;" : "=f"(y) : "f"(x));
    return y;
}

__device__ __forceinline__ void mma16816(float c[4], const unsigned a[4], const unsigned b[2]) {
    asm volatile(
        "mma.sync.aligned.m16n8k16.row.col.f32.bf16.bf16.f32 "
        "{%0,%1,%2,%3}, {%4,%5,%6,%7}, {%8,%9}, {%0,%1,%2,%3};"
        : "+f"(c[0]), "+f"(c[1]), "+f"(c[2]), "+f"(c[3])
        : "r"(a[0]), "r"(a[1]), "r"(a[2]), "r"(a[3]), "r"(b[0]), "r"(b[1]));
}

// ---------------------------------------------------------------------------
// K1: one warp per pair i. Computes s11, s22, s12 in one pass, writes both
// normalized rows as bf16 into g_H, pos dot (fp32), zeroes g_rowsum.
// ---------------------------------------------------------------------------
__global__ void norm_kernel(const float* __restrict__ h1, const float* __restrict__ h2) {
    const int gwarp = (blockIdx.x * blockDim.x + threadIdx.x) >> 5;
    const int lane  = threadIdx.x & 31;
    if (gwarp >= NPAIR) return;

    const float4 a = reinterpret_cast<const float4*>(h1 + (size_t)gwarp * D)[lane];
    const float4 b = reinterpret_cast<const float4*>(h2 + (size_t)gwarp * D)[lane];

    float s11 = a.x * a.x + a.y * a.y + a.z * a.z + a.w * a.w;
    float s22 = b.x * b.x + b.y * b.y + b.z * b.z + b.w * b.w;
    float s12 = a.x * b.x + a.y * b.y + a.z * b.z + a.w * b.w;

    #pragma unroll
    for (int off = 16; off > 0; off >>= 1) {
        s11 += __shfl_xor_sync(0xffffffffu, s11, off);
        s22 += __shfl_xor_sync(0xffffffffu, s22, off);
        s12 += __shfl_xor_sync(0xffffffffu, s12, off);
    }

    const float i1 = rsqrtf(s11);
    const float i2 = rsqrtf(s22);

    __nv_bfloat162* r1 = reinterpret_cast<__nv_bfloat162*>(g_H + (size_t)gwarp * D);
    __nv_bfloat162* r2 = reinterpret_cast<__nv_bfloat162*>(g_H + (size_t)(gwarp + NPAIR) * D);
    r1[lane * 2 + 0] = __floats2bfloat162_rn(a.x * i1, a.y * i1);
    r1[lane * 2 + 1] = __floats2bfloat162_rn(a.z * i1, a.w * i1);
    r2[lane * 2 + 0] = __floats2bfloat162_rn(b.x * i2, b.y * i2);
    r2[lane * 2 + 1] = __floats2bfloat162_rn(b.z * i2, b.w * i2);

    if (lane == 0) {
        g_pos[gwarp] = s12 * i1 * i2;
        g_rowsum[gwarp] = 0.0f;
        g_rowsum[gwarp + NPAIR] = 0.0f;
    }
}

// ---------------------------------------------------------------------------
// K2: one CTA per upper-triangular 128x128 tile (bj >= bi), K=128 one shot.
// 4 warps (2x2), 64x64 warp tile, m16n8k16 bf16 mma.
// Epilogue: exp(2*s) in place, then
//   - row reduce    -> atomicAdd(g_rowsum[bi-block rows])
//   - col reduce    -> atomicAdd(g_rowsum[bj-block rows])  (off-diag only)
// ---------------------------------------------------------------------------
__global__ void __launch_bounds__(128) gemm_kernel() {
    extern __shared__ __nv_bfloat16 smem[];
    __nv_bfloat16* sA = smem;               // 128 x LDT
    __nv_bfloat16* sB = smem + 128 * LDT;   // 128 x LDT

    const int tid = threadIdx.x;

    // decode linear tile index p -> (bi, bj) with bj >= bi
    // f(bi) = #tiles before row bi = bi*(2*NTILE+1-bi)/2
    const int p = blockIdx.x;
    int bi = (int)(128.5 - sqrt(128.5 * 128.5 - 2.0 * (double)p));
    if (bi > 0 && bi * (257 - bi) / 2 > p) --bi;
    if ((bi + 1) * (256 - bi) / 2 <= p) ++bi;
    const int bj = bi + (p - bi * (257 - bi) / 2);

    // load both 128x128 bf16 tiles (rows of H), coalesced 16B chunks
    #pragma unroll
    for (int i = tid; i < 128 * 16; i += 128) {
        const int r = i >> 4, c = i & 15;
        *reinterpret_cast<uint4*>(sA + r * LDT + c * 8) =
            *reinterpret_cast<const uint4*>(g_H + (size_t)(bi * 128 + r) * D + c * 8);
        *reinterpret_cast<uint4*>(sB + r * LDT + c * 8) =
            *reinterpret_cast<const uint4*>(g_H + (size_t)(bj * 128 + r) * D + c * 8);
    }
    __syncthreads();

    const int warp = tid >> 5;
    const int lane = tid & 31;
    const int wm = warp >> 1;       // 0..1
    const int wn = warp & 1;        // 0..1
    const int g  = lane >> 2;       // 0..7
    const int tg = lane & 3;        // 0..3

    float acc[4][8][4];
    #pragma unroll
    for (int f = 0; f < 4; ++f)
        #pragma unroll
        for (int j = 0; j < 8; ++j)
            #pragma unroll
            for (int q = 0; q < 4; ++q) acc[f][j][q] = 0.0f;

    const __nv_bfloat16* Ab = sA + (wm * 64) * LDT;
    const __nv_bfloat16* Bb = sB + (wn * 64) * LDT;

    #pragma unroll
    for (int k = 0; k < 8; ++k) {
        const int k0 = k * 16 + tg * 2;
        unsigned a[4][4], b[8][2];
        #pragma unroll
        for (int f = 0; f < 4; ++f) {
            const __nv_bfloat16* p2 = Ab + (f * 16 + g) * LDT + k0;
            a[f][0] = *reinterpret_cast<const unsigned*>(p2);
            a[f][1] = *reinterpret_cast<const unsigned*>(p2 + 8 * LDT);
            a[f][2] = *reinterpret_cast<const unsigned*>(p2 + 8);
            a[f][3] = *reinterpret_cast<const unsigned*>(p2 + 8 * LDT + 8);
        }
        #pragma unroll
        for (int j = 0; j < 8; ++j) {
            const __nv_bfloat16* p2 = Bb + (j * 8 + g) * LDT + k0;
            b[j][0] = *reinterpret_cast<const unsigned*>(p2);
            b[j][1] = *reinterpret_cast<const unsigned*>(p2 + 8);
        }
        #pragma unroll
        for (int f = 0; f < 4; ++f)
            #pragma unroll
            for (int j = 0; j < 8; ++j)
                mma16816(acc[f][j], a[f], b[j]);
    }

    // exp(s/t) = exp(2 s) = 2^(2 log2e * s), in place
    const float KK = 2.8853900817779268f;
    #pragma unroll
    for (int f = 0; f < 4; ++f)
        #pragma unroll
        for (int j = 0; j < 8; ++j)
            #pragma unroll
            for (int q = 0; q < 4; ++q)
                acc[f][j][q] = ex2f(acc[f][j][q] * KK);

    // ---- row sums -> bi-block ----
    // thread holds rows (f*16+g) via q=0,1 and (f*16+8+g) via q=2,3
    #pragma unroll
    for (int f = 0; f < 4; ++f) {
        float slo = 0.0f, shi = 0.0f;
        #pragma unroll
        for (int j = 0; j < 8; ++j) {
            slo += acc[f][j][0] + acc[f][j][1];
            shi += acc[f][j][2] + acc[f][j][3];
        }
        slo += __shfl_xor_sync(0xffffffffu, slo, 1);
        slo += __shfl_xor_sync(0xffffffffu, slo, 2);
        shi += __shfl_xor_sync(0xffffffffu, shi, 1);
        shi += __shfl_xor_sync(0xffffffffu, shi, 2);
        if (tg == 0) {
            const int row = bi * 128 + wm * 64 + f * 16 + g;
            atomicAdd(&g_rowsum[row], slo);
            atomicAdd(&g_rowsum[row + 8], shi);
        }
    }

    // ---- column sums -> bj-block (symmetry), off-diagonal tiles only ----
    // thread holds cols (j*8+2tg) via q=0,2 and (j*8+2tg+1) via q=1,3
    if (bj != bi) {
        #pragma unroll
        for (int j = 0; j < 8; ++j) {
            float c0 = 0.0f, c1 = 0.0f;
            #pragma unroll
            for (int f = 0; f < 4; ++f) {
                c0 += acc[f][j][0] + acc[f][j][2];
                c1 += acc[f][j][1] + acc[f][j][3];
            }
            c0 += __shfl_xor_sync(0xffffffffu, c0, 4);
            c0 += __shfl_xor_sync(0xffffffffu, c0, 8);
            c0 += __shfl_xor_sync(0xffffffffu, c0, 16);
            c1 += __shfl_xor_sync(0xffffffffu, c1, 4);
            c1 += __shfl_xor_sync(0xffffffffu, c1, 8);
            c1 += __shfl_xor_sync(0xffffffffu, c1, 16);
            if (g == 0) {
                const int col = bj * 128 + wn * 64 + j * 8 + 2 * tg;
                atomicAdd(&g_rowsum[col], c0);
                atomicAdd(&g_rowsum[col + 1], c1);
            }
        }
    }
}

// ---------------------------------------------------------------------------
// K3: loss = mean( log(rowsum_i - e^2) - 2 * pos[i mod NPAIR] )
// ---------------------------------------------------------------------------
__global__ void loss_kernel(float* __restrict__ out) {
    __shared__ float red[256];
    const float E2 = 7.389056098930650f;  // exp(1/t) = e^2
    float s = 0.0f;
    for (int i = threadIdx.x; i < NROWS; i += 256) {
        const float denom = g_rowsum[i] - E2;
        s += logf(denom) - 2.0f * g_pos[i & (NPAIR - 1)];
    }
    red[threadIdx.x] = s;
    __syncthreads();
    #pragma unroll
    for (int off = 128; off > 0; off >>= 1) {
        if (threadIdx.x < off) red[threadIdx.x] += red[threadIdx.x + off];
        __syncthreads();
    }
    if (threadIdx.x == 0) out[0] = red[0] * (1.0f / (float)NROWS);
}

extern "C" void kernel_launch(void* const* d_in, const int* in_sizes, int n_in,
                              void* d_out, int out_size) {
    const float* h1 = (const float*)d_in[0];
    const float* h2 = (const float*)d_in[1];

    cudaFuncSetAttribute(gemm_kernel, cudaFuncAttributeMaxDynamicSharedMemorySize,
                         (int)SMEM_BYTES);

    norm_kernel<<<NPAIR / 8, 256>>>(h1, h2);
    gemm_kernel<<<NTRI, 128, SMEM_BYTES>>>();
    loss_kernel<<<1, 256>>>((float*)d_out);
}

// round 13
// speedup vs baseline: 1.4908x; 1.0359x over previous
#include <cuda_runtime.h>
#include <cuda_bf16.h>
#include <cuda_fp8.h>
#include <cstdint>
#include <stdint.h>
#include <math.h>

// NTXent loss, t = 0.5 — FP8 (e4m3) legacy-mma version.
// tcgen05 is unavailable: this harness's PTX targets baseline sm_103 (no 'a').
//
// K1: normalize h1/h2 rows -> e4m3 H8[16384][128], fp32 pos dots, zero rowsums
// K2: one CTA per upper-triangular 128x128 tile of S = H H^T.
//     mma.sync.m16n8k32.e4m3 (fp32 accum), 4 warps, 64x64 warp tiles,
//     K=128 in 4 k-steps. Epilogue: exp(2s) via ex2, row sums -> bi rows,
//     column sums -> bj rows (symmetry of S).
// K3: final log + mean reduction.
//
// Diagonal of exp(S/t) ~ e^2 (normalized rows); included in sums, subtracted.

#define NROWS 16384
#define NPAIR 8192
#define D     128

#define NTILE 128                         // 16384 / 128
#define NTRI  (NTILE * (NTILE + 1) / 2)   // 8256 upper-tri tiles

__device__ __align__(16) uint8_t g_H8[(size_t)NROWS * D];   // e4m3
__device__ float g_rowsum[NROWS];
__device__ float g_pos[NPAIR];

__device__ __forceinline__ float ex2f(float x) {
    float y;
    asm("ex2.approx.ftz.f32 %0, %1;" : "=f"(y) : "f"(x));
    return y;
}

// pack 2 floats -> e4m3x2 (lo = second source operand)
__device__ __forceinline__ unsigned short fp8x2(float lo, float hi) {
    unsigned short q;
    asm("cvt.rn.satfinite.e4m3x2.f32 %0, %1, %2;" : "=h"(q) : "f"(hi), "f"(lo));
    return q;
}

__device__ __forceinline__ void mma16832(float c[4], const unsigned a[4], const unsigned b[2]) {
    asm volatile(
        "mma.sync.aligned.m16n8k32.row.col.f32.e4m3.e4m3.f32 "
        "{%0,%1,%2,%3}, {%4,%5,%6,%7}, {%8,%9}, {%0,%1,%2,%3};"
        : "+f"(c[0]), "+f"(c[1]), "+f"(c[2]), "+f"(c[3])
        : "r"(a[0]), "r"(a[1]), "r"(a[2]), "r"(a[3]), "r"(b[0]), "r"(b[1]));
}

// ---------------------------------------------------------------------------
// K1: one warp per pair i. fp32 norms/dots, fp8 outputs.
// ---------------------------------------------------------------------------
__global__ void norm_kernel(const float* __restrict__ h1, const float* __restrict__ h2) {
    const int gwarp = (blockIdx.x * blockDim.x + threadIdx.x) >> 5;
    const int lane  = threadIdx.x & 31;
    if (gwarp >= NPAIR) return;

    const float4 a = reinterpret_cast<const float4*>(h1 + (size_t)gwarp * D)[lane];
    const float4 b = reinterpret_cast<const float4*>(h2 + (size_t)gwarp * D)[lane];

    float s11 = a.x * a.x + a.y * a.y + a.z * a.z + a.w * a.w;
    float s22 = b.x * b.x + b.y * b.y + b.z * b.z + b.w * b.w;
    float s12 = a.x * b.x + a.y * b.y + a.z * b.z + a.w * b.w;

    #pragma unroll
    for (int off = 16; off > 0; off >>= 1) {
        s11 += __shfl_xor_sync(0xffffffffu, s11, off);
        s22 += __shfl_xor_sync(0xffffffffu, s22, off);
        s12 += __shfl_xor_sync(0xffffffffu, s12, off);
    }

    const float i1 = rsqrtf(s11);
    const float i2 = rsqrtf(s22);

    // 4 e4m3 bytes per lane per row (elements 4*lane .. 4*lane+3)
    const unsigned w1 = (unsigned)fp8x2(a.x * i1, a.y * i1) |
                        ((unsigned)fp8x2(a.z * i1, a.w * i1) << 16);
    const unsigned w2 = (unsigned)fp8x2(b.x * i2, b.y * i2) |
                        ((unsigned)fp8x2(b.z * i2, b.w * i2) << 16);

    reinterpret_cast<unsigned*>(g_H8 + (size_t)gwarp * D)[lane] = w1;
    reinterpret_cast<unsigned*>(g_H8 + (size_t)(gwarp + NPAIR) * D)[lane] = w2;

    if (lane == 0) {
        g_pos[gwarp] = s12 * i1 * i2;
        g_rowsum[gwarp] = 0.0f;
        g_rowsum[gwarp + NPAIR] = 0.0f;
    }
}

// ---------------------------------------------------------------------------
// K2: fp8 tile kernel. 128 threads (4 warps), static smem 32KB -> 2+ CTAs/SM.
//
// SMEM layout: rows of 128 bytes, rotated by 16*row bytes (mod 128).
// Fragment accesses (4B at logical byte k0 + tg*4 (+16), row base+g) then hit
// word tg + 4*g (mod 32): a perfect bank bijection -> conflict-free.
// ---------------------------------------------------------------------------
__device__ __forceinline__ uint32_t rot_off(int row, int byte) {
    return (uint32_t)(row * 128 + ((byte + (row << 4)) & 127));
}

__global__ void __launch_bounds__(128) gemm_kernel() {
    __shared__ __align__(16) uint8_t sA[128 * 128];
    __shared__ __align__(16) uint8_t sB[128 * 128];

    const int tid = threadIdx.x;

    // decode linear tile index p -> (bi, bj), bj >= bi
    const int p = blockIdx.x;
    int bi = (int)(128.5 - sqrt(128.5 * 128.5 - 2.0 * (double)p));
    if (bi > 0 && bi * (257 - bi) / 2 > p) --bi;
    if ((bi + 1) * (256 - bi) / 2 <= p) ++bi;
    const int bj = bi + (p - bi * (257 - bi) / 2);

    // load tiles: 128 rows x 8 chunks of 16B, rotated placement
    #pragma unroll
    for (int i = tid; i < 128 * 8; i += 128) {
        const int r = i >> 3, c = i & 7;
        const uint32_t dst = (uint32_t)(r * 128 + (((c + r) & 7) << 4));
        *reinterpret_cast<uint4*>(sA + dst) =
            *reinterpret_cast<const uint4*>(g_H8 + (size_t)(bi * 128 + r) * D + c * 16);
        *reinterpret_cast<uint4*>(sB + dst) =
            *reinterpret_cast<const uint4*>(g_H8 + (size_t)(bj * 128 + r) * D + c * 16);
    }
    __syncthreads();

    const int warp = tid >> 5;
    const int lane = tid & 31;
    const int wm = warp >> 1;       // 0..1
    const int wn = warp & 1;        // 0..1
    const int g  = lane >> 2;       // 0..7
    const int tg = lane & 3;        // 0..3

    float acc[4][8][4];
    #pragma unroll
    for (int f = 0; f < 4; ++f)
        #pragma unroll
        for (int j = 0; j < 8; ++j)
            #pragma unroll
            for (int q = 0; q < 4; ++q) acc[f][j][q] = 0.0f;

    #pragma unroll
    for (int k = 0; k < 4; ++k) {       // K = 4 x 32
        const int k0 = k * 32 + tg * 4;
        unsigned a[4][4], b[8][2];
        #pragma unroll
        for (int f = 0; f < 4; ++f) {
            const int r0 = wm * 64 + f * 16 + g;
            const int r1 = r0 + 8;
            a[f][0] = *reinterpret_cast<const unsigned*>(sA + rot_off(r0, k0));
            a[f][1] = *reinterpret_cast<const unsigned*>(sA + rot_off(r1, k0));
            a[f][2] = *reinterpret_cast<const unsigned*>(sA + rot_off(r0, k0 + 16));
            a[f][3] = *reinterpret_cast<const unsigned*>(sA + rot_off(r1, k0 + 16));
        }
        #pragma unroll
        for (int j = 0; j < 8; ++j) {
            const int rn = wn * 64 + j * 8 + g;
            b[j][0] = *reinterpret_cast<const unsigned*>(sB + rot_off(rn, k0));
            b[j][1] = *reinterpret_cast<const unsigned*>(sB + rot_off(rn, k0 + 16));
        }
        #pragma unroll
        for (int f = 0; f < 4; ++f)
            #pragma unroll
            for (int j = 0; j < 8; ++j)
                mma16832(acc[f][j], a[f], b[j]);
    }

    // exp(s/t) = exp(2 s) = 2^(2 log2e * s), in place
    const float KK = 2.8853900817779268f;
    #pragma unroll
    for (int f = 0; f < 4; ++f)
        #pragma unroll
        for (int j = 0; j < 8; ++j)
            #pragma unroll
            for (int q = 0; q < 4; ++q)
                acc[f][j][q] = ex2f(acc[f][j][q] * KK);

    // ---- row sums -> bi block ----
    // thread holds rows (f*16+g) via q=0,1 and (f*16+8+g) via q=2,3
    #pragma unroll
    for (int f = 0; f < 4; ++f) {
        float slo = 0.0f, shi = 0.0f;
        #pragma unroll
        for (int j = 0; j < 8; ++j) {
            slo += acc[f][j][0] + acc[f][j][1];
            shi += acc[f][j][2] + acc[f][j][3];
        }
        slo += __shfl_xor_sync(0xffffffffu, slo, 1);
        slo += __shfl_xor_sync(0xffffffffu, slo, 2);
        shi += __shfl_xor_sync(0xffffffffu, shi, 1);
        shi += __shfl_xor_sync(0xffffffffu, shi, 2);
        if (tg == 0) {
            const int row = bi * 128 + wm * 64 + f * 16 + g;
            atomicAdd(&g_rowsum[row], slo);
            atomicAdd(&g_rowsum[row + 8], shi);
        }
    }

    // ---- column sums -> bj block (symmetry), off-diagonal tiles only ----
    // thread holds cols (j*8+2tg) via q=0,2 and (j*8+2tg+1) via q=1,3
    if (bj != bi) {
        #pragma unroll
        for (int j = 0; j < 8; ++j) {
            float c0 = 0.0f, c1 = 0.0f;
            #pragma unroll
            for (int f = 0; f < 4; ++f) {
                c0 += acc[f][j][0] + acc[f][j][2];
                c1 += acc[f][j][1] + acc[f][j][3];
            }
            c0 += __shfl_xor_sync(0xffffffffu, c0, 4);
            c0 += __shfl_xor_sync(0xffffffffu, c0, 8);
            c0 += __shfl_xor_sync(0xffffffffu, c0, 16);
            c1 += __shfl_xor_sync(0xffffffffu, c1, 4);
            c1 += __shfl_xor_sync(0xffffffffu, c1, 8);
            c1 += __shfl_xor_sync(0xffffffffu, c1, 16);
            if (g == 0) {
                const int col = bj * 128 + wn * 64 + j * 8 + 2 * tg;
                atomicAdd(&g_rowsum[col], c0);
                atomicAdd(&g_rowsum[col + 1], c1);
            }
        }
    }
}

// ---------------------------------------------------------------------------
// K3: loss = mean( log(rowsum_i - e^2) - 2 * pos[i mod NPAIR] )
// ---------------------------------------------------------------------------
__global__ void loss_kernel(float* __restrict__ out) {
    __shared__ float red[256];
    const float E2 = 7.389056098930650f;  // exp(1/t) = e^2
    float s = 0.0f;
    for (int i = threadIdx.x; i < NROWS; i += 256) {
        const float denom = g_rowsum[i] - E2;
        s += logf(denom) - 2.0f * g_pos[i & (NPAIR - 1)];
    }
    red[threadIdx.x] = s;
    __syncthreads();
    #pragma unroll
    for (int off = 128; off > 0; off >>= 1) {
        if (threadIdx.x < off) red[threadIdx.x] += red[threadIdx.x + off];
        __syncthreads();
    }
    if (threadIdx.x == 0) out[0] = red[0] * (1.0f / (float)NROWS);
}

extern "C" void kernel_launch(void* const* d_in, const int* in_sizes, int n_in,
                              void* d_out, int out_size) {
    const float* h1 = (const float*)d_in[0];
    const float* h2 = (const float*)d_in[1];

    norm_kernel<<<NPAIR / 8, 256>>>(h1, h2);
    gemm_kernel<<<NTRI, 128>>>();
    loss_kernel<<<1, 256>>>((float*)d_out);
}